// round 2
// baseline (speedup 1.0000x reference)
#include <cuda_runtime.h>
#include <math.h>

#define T_STEPS 512
#define BATCH   64
#define NINP_D  512
#define NHID_D  1024
#define NGATE   4096   // 4*NHID
#define NCTA_R  128    // recurrence CTAs (<= SM count -> co-resident, barrier-safe)
#define UPC     8      // hidden units per recurrence CTA

typedef unsigned long long ull;

// ---------------- scratch (device globals; no runtime allocation) ----------
__device__ float g_xw_enc[(size_t)T_STEPS * BATCH * NGATE]; // 512 MB
__device__ float g_xw_dec[(size_t)T_STEPS * BATCH * NGATE]; // 512 MB
__device__ float g_Wt_enc[(size_t)NHID_D * NGATE];          // W_hh^T: [k][gatecol]
__device__ float g_Wt_dec[(size_t)NHID_D * NGATE];
__device__ float g_ht[2][NHID_D * BATCH];                   // h transposed [u][b], ping-pong
__device__ float g_ct[NHID_D * BATCH];                      // c transposed [u][b]
__device__ unsigned g_arrive;
__device__ unsigned g_release;

// ---------------- f32x2 helpers --------------------------------------------
__device__ __forceinline__ void ffma2(ull& d, ull a, ull b) {
    asm("fma.rn.f32x2 %0, %1, %2, %0;" : "+l"(d) : "l"(a), "l"(b));
}
__device__ __forceinline__ float2 unpack2(ull v) {
    float2 r; asm("mov.b64 {%0,%1}, %2;" : "=f"(r.x), "=f"(r.y) : "l"(v)); return r;
}

// ---------------- init: zero state + barrier counters ----------------------
__global__ void init_state() {
    int i = blockIdx.x * blockDim.x + threadIdx.x;
    if (i == 0) { g_arrive = 0; g_release = 0; }
    if (i < NHID_D * BATCH) {
        g_ht[0][i] = 0.f;
        g_ht[1][i] = 0.f;
        g_ct[i]    = 0.f;
    }
}

// ---------------- transpose W_hh [4096][1024] -> Wt [1024][4096] -----------
__global__ void transpose_w(const float* __restrict__ W, int which) {
    float* Wt = which ? g_Wt_dec : g_Wt_enc;
    __shared__ float tile[32][33];
    int j0 = blockIdx.x * 32;   // gate col 0..4095
    int k0 = blockIdx.y * 32;   // hidden k 0..1023
    int x = threadIdx.x, y = threadIdx.y;  // block (32,8)
    #pragma unroll
    for (int i = 0; i < 32; i += 8)
        tile[y + i][x] = W[(size_t)(j0 + y + i) * NHID_D + k0 + x];
    __syncthreads();
    #pragma unroll
    for (int i = 0; i < 32; i += 8)
        Wt[(size_t)(k0 + y + i) * NGATE + j0 + x] = tile[x][y + i];
}

// ---------------- phase 1: xW = input @ W_ih^T + b_ih (f32x2 GEMM) ---------
// C[m][n] = sum_k A[m][k]*W[n][k] + bias[n]; 64x64 tile, thread = 4m x 4n,
// n accumulated as 2 f32x2 pairs.
__global__ __launch_bounds__(256) void gemm_xw(const float* __restrict__ A,
                                               const float* __restrict__ W,
                                               const float* __restrict__ bias,
                                               int which) {
    float* C = which ? g_xw_dec : g_xw_enc;
    __shared__ float2 Asd[64][17];   // [slot][kk], (a,a) duplicated; slot(r)=(r&3)*16+(r>>2)
    __shared__ float  Bs[16][66];    // [kk][r]
    int m0 = blockIdx.y * 64, n0 = blockIdx.x * 64;
    int t = threadIdx.x;
    int tm = t & 15, tn = t >> 4;
    ull acc[4][2];
    #pragma unroll
    for (int i = 0; i < 4; i++) { acc[i][0] = 0ULL; acc[i][1] = 0ULL; }

    for (int k0 = 0; k0 < NINP_D; k0 += 16) {
        __syncthreads();
        #pragma unroll
        for (int i = 0; i < 4; i++) {
            int idx = t + 256 * i;
            int kk = idx & 15, r = idx >> 4;            // r: 0..63
            float a = A[(size_t)(m0 + r) * NINP_D + k0 + kk];
            Asd[(r & 3) * 16 + (r >> 2)][kk] = make_float2(a, a);
            Bs[kk][r] = W[(size_t)(n0 + r) * NINP_D + k0 + kk];
        }
        __syncthreads();
        #pragma unroll
        for (int kk = 0; kk < 16; kk++) {
            ull b0 = *(const ull*)&Bs[kk][tn * 4];
            ull b1 = *(const ull*)&Bs[kk][tn * 4 + 2];
            #pragma unroll
            for (int i = 0; i < 4; i++) {
                ull a2 = *(const ull*)&Asd[i * 16 + tm][kk];
                ffma2(acc[i][0], a2, b0);
                ffma2(acc[i][1], a2, b1);
            }
        }
    }
    #pragma unroll
    for (int i = 0; i < 4; i++) {
        int m = m0 + tm * 4 + i;
        #pragma unroll
        for (int j2 = 0; j2 < 2; j2++) {
            int n = n0 + tn * 4 + 2 * j2;
            float2 v = unpack2(acc[i][j2]);
            v.x += bias[n];
            v.y += bias[n + 1];
            *(float2*)&C[(size_t)m * NGATE + n] = v;
        }
    }
}

// ---------------- persistent recurrence ------------------------------------
// 128 CTAs x 256 threads. CTA owns units [u0, u0+8). Thread decomposition:
// b2 = t&31 (batch pair {2b2,2b2+1} packed in f32x2 lanes), g = (t>>5)&3,
// uh = t>>7 (units uh*4..uh*4+3). 8 MACs/kk/thread via 4 FFMA2.
__device__ __forceinline__ void grid_barrier(unsigned target) {
    __syncthreads();
    if (threadIdx.x == 0) {
        __threadfence();
        unsigned prev = atomicAdd(&g_arrive, 1);
        if (prev == target * (unsigned)gridDim.x - 1) {
            atomicExch(&g_release, target);
        } else {
            while (*(volatile unsigned*)&g_release < target) __nanosleep(32);
        }
        __threadfence();
    }
    __syncthreads();
}

__global__ __launch_bounds__(256) void rnn_persist(const float* __restrict__ b_hh_enc,
                                                   const float* __restrict__ b_hh_dec,
                                                   const float* __restrict__ mask,
                                                   float* __restrict__ out) {
    __shared__ float  hs[64][64];     // [kk][b]
    __shared__ float2 wsd[64][32];    // [kk][g*8+uu], (w,w) duplicated
    __shared__ float  gs[4][8][64];   // [gate][uu][b] pre-activations

    int t  = threadIdx.x;
    int u0 = blockIdx.x * UPC;
    int b2 = t & 31;
    int g  = (t >> 5) & 3;
    int uh = t >> 7;
    int col0 = g * NHID_D + u0 + (uh << 2);

    for (int gstep = 0; gstep < 2 * T_STEPS; gstep++) {
        int is_dec = gstep >= T_STEPS;
        int step   = gstep & (T_STEPS - 1);
        const float* xw    = (is_dec ? g_xw_dec : g_xw_enc) + (size_t)step * BATCH * NGATE;
        const float* Wt    = is_dec ? g_Wt_dec : g_Wt_enc;
        const float* bhh   = is_dec ? b_hh_dec : b_hh_enc;
        const float* ht_in = g_ht[gstep & 1];
        float*       ht_out = g_ht[(gstep + 1) & 1];

        // prefetch this thread's xw slice (streamed, L2-only)
        float4 xw0 = __ldcg((const float4*)(xw + (size_t)(2 * b2) * NGATE + col0));
        float4 xw1 = __ldcg((const float4*)(xw + (size_t)(2 * b2 + 1) * NGATE + col0));

        ull acc[4] = {0ULL, 0ULL, 0ULL, 0ULL};
        for (int k0 = 0; k0 < NHID_D; k0 += 64) {
            __syncthreads();
            // h tile (L2-only: cross-CTA coherence + no L1 pollution)
            const float4* hsrc = (const float4*)(ht_in + k0 * BATCH);
            #pragma unroll
            for (int i = 0; i < 4; i++)
                ((float4*)hs)[t + 256 * i] = __ldcg(hsrc + t + 256 * i);
            // W tile, duplicated for f32x2 (L1-cached: per-CTA footprint 128KB)
            #pragma unroll
            for (int i = 0; i < 8; i++) {
                int idx = t + 256 * i;
                int kk = idx >> 5, c = idx & 31;
                float w = Wt[(size_t)(k0 + kk) * NGATE + (c >> 3) * NHID_D + u0 + (c & 7)];
                wsd[kk][c] = make_float2(w, w);
            }
            __syncthreads();
            #pragma unroll 8
            for (int kk = 0; kk < 64; kk++) {
                ull hv2 = *(const ull*)&hs[kk][2 * b2];
                #pragma unroll
                for (int j = 0; j < 4; j++)
                    ffma2(acc[j], hv2, *(const ull*)&wsd[kk][(g << 3) + (uh << 2) + j]);
            }
        }

        // gates -> smem (add xw + b_hh)
        const float* xv0 = (const float*)&xw0;
        const float* xv1 = (const float*)&xw1;
        #pragma unroll
        for (int j = 0; j < 4; j++) {
            float2 a = unpack2(acc[j]);
            float bb_ = bhh[col0 + j];
            gs[g][(uh << 2) + j][2 * b2]     = a.x + xv0[j] + bb_;
            gs[g][(uh << 2) + j][2 * b2 + 1] = a.y + xv1[j] + bb_;
        }
        __syncthreads();

        // elementwise LSTM update: 512 (b,u) items, 2 per thread
        #pragma unroll
        for (int i = 0; i < 2; i++) {
            int idx = t + 256 * i;
            int uu = idx & 7, bb = idx >> 3;
            float gi = gs[0][uu][bb];
            float gf = gs[1][uu][bb];
            float gc = gs[2][uu][bb];
            float go = gs[3][uu][bb];
            gi = 1.f / (1.f + expf(-gi));
            gf = 1.f / (1.f + expf(-gf));
            gc = tanhf(gc);
            go = 1.f / (1.f + expf(-go));
            int u = u0 + uu;
            float c_old = g_ct[u * BATCH + bb];
            float c_new = fmaf(gf, c_old, gi * gc);
            float h_new = go * tanhf(c_new);
            if (!is_dec) {
                float m = mask[(size_t)step * BATCH + bb];   // exactly 0 or 1
                if (m == 0.f) {
                    h_new = __ldcg(&ht_in[u * BATCH + bb]);
                    c_new = c_old;
                }
            } else {
                out[((size_t)step * BATCH + bb) * NHID_D + u] = h_new;
            }
            g_ct[u * BATCH + bb] = c_new;
            __stcg(&ht_out[u * BATCH + bb], h_new);
        }

        grid_barrier((unsigned)(gstep + 1));
    }
}

// ---------------- launch ----------------------------------------------------
extern "C" void kernel_launch(void* const* d_in, const int* in_sizes, int n_in,
                              void* d_out, int out_size) {
    const float* input    = (const float*)d_in[0];  // [512,64,512]
    const float* mask     = (const float*)d_in[1];  // [512,64]
    const float* W_ih_enc = (const float*)d_in[2];  // [4096,512]
    const float* W_hh_enc = (const float*)d_in[3];  // [4096,1024]
    const float* b_ih_enc = (const float*)d_in[4];  // [4096]
    const float* b_hh_enc = (const float*)d_in[5];  // [4096]
    const float* W_ih_dec = (const float*)d_in[6];
    const float* W_hh_dec = (const float*)d_in[7];
    const float* b_ih_dec = (const float*)d_in[8];
    const float* b_hh_dec = (const float*)d_in[9];
    float* out = (float*)d_out;                     // [32768,1024]

    init_state<<<(NHID_D * BATCH + 255) / 256, 256>>>();

    dim3 tg(NGATE / 32, NHID_D / 32), tb(32, 8);
    transpose_w<<<tg, tb>>>(W_hh_enc, 0);
    transpose_w<<<tg, tb>>>(W_hh_dec, 1);

    dim3 gg(NGATE / 64, (T_STEPS * BATCH) / 64);
    gemm_xw<<<gg, 256>>>(input, W_ih_enc, b_ih_enc, 0);
    gemm_xw<<<gg, 256>>>(input, W_ih_dec, b_ih_dec, 1);

    rnn_persist<<<NCTA_R, 256>>>(b_hh_enc, b_hh_dec, mask, out);
}

// round 3
// speedup vs baseline: 2.7771x; 2.7771x over previous
#include <cuda_runtime.h>
#include <math.h>

#define T_STEPS 512
#define BATCH   64
#define NINP_D  512
#define NHID_D  1024
#define NGATE   4096   // 4*NHID
#define NCTA_R  128

typedef unsigned long long ull;

// ---------------- scratch (device globals; no runtime allocation) ----------
__device__ float g_xw_enc[(size_t)T_STEPS * BATCH * NGATE]; // 512 MB
__device__ float g_xw_dec[(size_t)T_STEPS * BATCH * NGATE]; // 512 MB
__device__ float g_h[2][BATCH * NHID_D];                    // h [b][u], ping-pong
__device__ unsigned g_arrive;
__device__ unsigned g_release;

// ---------------- helpers ---------------------------------------------------
__device__ __forceinline__ void ffma2(ull& d, ull a, ull b) {
    asm("fma.rn.f32x2 %0, %1, %2, %0;" : "+l"(d) : "l"(a), "l"(b));
}
__device__ __forceinline__ float2 unpack2(ull v) {
    float2 r; asm("mov.b64 {%0,%1}, %2;" : "=f"(r.x), "=f"(r.y) : "l"(v)); return r;
}
__device__ __forceinline__ void cp_async16(unsigned s, const void* g) {
    asm volatile("cp.async.cg.shared.global [%0], [%1], 16;" :: "r"(s), "l"(g));
}
__device__ __forceinline__ void cp_commit() { asm volatile("cp.async.commit_group;"); }
__device__ __forceinline__ void cp_wait0()  { asm volatile("cp.async.wait_group 0;" ::: "memory"); }

// ---------------- init ------------------------------------------------------
__global__ void init_state() {
    int i = blockIdx.x * blockDim.x + threadIdx.x;
    if (i == 0) { g_arrive = 0; g_release = 0; }
    if (i < BATCH * NHID_D) { g_h[0][i] = 0.f; g_h[1][i] = 0.f; }
}

// ---------------- phase 1: xW = input @ W_ih^T + b_ih ----------------------
// kk-pair f32x2 GEMM. 64x64 tile, 256 threads, thread = m{tm+16i} x n{4tn+j}.
// Per 4kk: 4 A-LDS.128 + 4 B-LDS.128 + 32 FFMA2 (FFMA2-pipe-bound).
__global__ __launch_bounds__(256) void gemm_xw(const float* __restrict__ A,
                                               const float* __restrict__ W,
                                               const float* __restrict__ bias,
                                               int which) {
    float* C = which ? g_xw_dec : g_xw_enc;
    __shared__ float As[64][36];   // stride 36 floats = 9 quads -> 1-quad shift/row
    __shared__ float Bs[64][36];
    int m0 = blockIdx.y * 64, n0 = blockIdx.x * 64;
    int t = threadIdx.x, tm = t & 15, tn = t >> 4;
    int lr = t >> 2, lc = (t & 3) * 8;      // loader: row lr, floats [lc, lc+8)

    ull acc[4][4];
    #pragma unroll
    for (int i = 0; i < 4; i++)
        #pragma unroll
        for (int j = 0; j < 4; j++) acc[i][j] = 0ULL;

    for (int k0 = 0; k0 < NINP_D; k0 += 32) {
        float4 a0 = *(const float4*)&A[(size_t)(m0 + lr) * NINP_D + k0 + lc];
        float4 a1 = *(const float4*)&A[(size_t)(m0 + lr) * NINP_D + k0 + lc + 4];
        float4 b0 = *(const float4*)&W[(size_t)(n0 + lr) * NINP_D + k0 + lc];
        float4 b1 = *(const float4*)&W[(size_t)(n0 + lr) * NINP_D + k0 + lc + 4];
        __syncthreads();
        *(float4*)&As[lr][lc]     = a0;
        *(float4*)&As[lr][lc + 4] = a1;
        *(float4*)&Bs[lr][lc]     = b0;
        *(float4*)&Bs[lr][lc + 4] = b1;
        __syncthreads();
        #pragma unroll
        for (int kk = 0; kk < 32; kk += 4) {
            ulonglong2 bv[4];
            #pragma unroll
            for (int j = 0; j < 4; j++)
                bv[j] = *(const ulonglong2*)&Bs[4 * tn + j][kk];
            #pragma unroll
            for (int i = 0; i < 4; i++) {
                ulonglong2 av = *(const ulonglong2*)&As[tm + 16 * i][kk];
                #pragma unroll
                for (int j = 0; j < 4; j++) {
                    ffma2(acc[i][j], av.x, bv[j].x);
                    ffma2(acc[i][j], av.y, bv[j].y);
                }
            }
        }
    }
    float4 bb = *(const float4*)&bias[n0 + 4 * tn];
    #pragma unroll
    for (int i = 0; i < 4; i++) {
        float2 p0 = unpack2(acc[i][0]);
        float2 p1 = unpack2(acc[i][1]);
        float2 p2 = unpack2(acc[i][2]);
        float2 p3 = unpack2(acc[i][3]);
        float4 o;
        o.x = p0.x + p0.y + bb.x;
        o.y = p1.x + p1.y + bb.y;
        o.z = p2.x + p2.y + bb.z;
        o.w = p3.x + p3.y + bb.w;
        *(float4*)&C[(size_t)(m0 + tm + 16 * i) * NGATE + n0 + 4 * tn] = o;
    }
}

// ---------------- grid barrier (validated in R2) ----------------------------
__device__ __forceinline__ void grid_barrier(unsigned target) {
    __threadfence();
    __syncthreads();
    if (threadIdx.x == 0) {
        unsigned prev = atomicAdd(&g_arrive, 1);
        if (prev == target * (unsigned)NCTA_R - 1) {
            atomicExch(&g_release, target);
        } else {
            while (*(volatile unsigned*)&g_release < target) __nanosleep(32);
        }
        __threadfence();
    }
    __syncthreads();
}

// ---------------- persistent recurrence ------------------------------------
// 128 CTAs x 256 threads. CTA owns 8 units (all 4 gates). Thread: unit u0+cg,
// batches {bg, bg+32}. W_hh direction slice resident in smem (132KB);
// h tile double-buffered via cp.async.cg. c,h thread-private registers.
#define WS_STRIDE 1028          // 1024 + 4 pad  (1-quad shift/row, 16B aligned)
#define HS_STRIDE 132           // 128 + 4 pad
#define HS_SIZE   (64 * HS_STRIDE)

extern __shared__ float smem_dyn[];

__global__ __launch_bounds__(256) void rnn_persist(
        const float* __restrict__ W_enc, const float* __restrict__ W_dec,
        const float* __restrict__ bhh_enc, const float* __restrict__ bhh_dec,
        const float* __restrict__ mask, float* __restrict__ out) {
    float* ws  = smem_dyn;                       // [32][WS_STRIDE]
    float* hsm = smem_dyn + 32 * WS_STRIDE;      // [2][64][HS_STRIDE]

    int t  = threadIdx.x;
    int cg = t & 7;            // unit within CTA
    int bg = t >> 3;           // batch group 0..31
    int u  = blockIdx.x * 8 + cg;
    int b0 = bg, b1 = bg + 32;

    float bE[4], bD[4];
    #pragma unroll
    for (int g = 0; g < 4; g++) {
        bE[g] = bhh_enc[g * NHID_D + u];
        bD[g] = bhh_dec[g * NHID_D + u];
    }
    int wrow[4];
    #pragma unroll
    for (int g = 0; g < 4; g++) wrow[g] = (g * 8 + cg) * WS_STRIDE;

    float creg[2] = {0.f, 0.f};
    float hreg[2] = {0.f, 0.f};
    unsigned hs_base = (unsigned)__cvta_generic_to_shared(hsm);

    for (int gstep = 0; gstep < 2 * T_STEPS; gstep++) {
        int is_dec = gstep >= T_STEPS;
        int step   = gstep & (T_STEPS - 1);
        const float* ht_in  = g_h[gstep & 1];
        float*       ht_out = g_h[(gstep + 1) & 1];
        const float* xw = (is_dec ? g_xw_dec : g_xw_enc) + (size_t)step * BATCH * NGATE;

        // load direction's W slice into smem once
        if (gstep == 0 || gstep == T_STEPS) {
            const float* Wh = is_dec ? W_dec : W_enc;
            int c = t >> 3;                                   // 32 rows, 8 thr/row
            const float* src = Wh + (size_t)((c >> 3) * NHID_D + blockIdx.x * 8 + (c & 7)) * NHID_D;
            float* dst = ws + c * WS_STRIDE;
            #pragma unroll
            for (int j = 0; j < 32; j++) {
                int off = j * 32 + (t & 7) * 4;
                *(float4*)&dst[off] = *(const float4*)&src[off];
            }
            __syncthreads();
        }

        // prefetch this thread's xw + mask (stream, L2-only)
        float xv0[4], xv1[4];
        #pragma unroll
        for (int g = 0; g < 4; g++) {
            xv0[g] = __ldcg(&xw[(size_t)b0 * NGATE + g * NHID_D + u]);
            xv1[g] = __ldcg(&xw[(size_t)b1 * NGATE + g * NHID_D + u]);
        }
        float m0v = 1.f, m1v = 1.f;
        if (!is_dec) {
            m0v = __ldg(&mask[(size_t)step * BATCH + b0]);
            m1v = __ldg(&mask[(size_t)step * BATCH + b1]);
        }

        // issue cp.async for h block 0
        #pragma unroll
        for (int i = 0; i < 8; i++) {
            int id = t + 256 * i, row = id >> 5, ck = id & 31;
            cp_async16(hs_base + (unsigned)(row * HS_STRIDE + ck * 4) * 4,
                       ht_in + row * NHID_D + ck * 4);
        }
        cp_commit();

        ull acc[4][2];
        #pragma unroll
        for (int g = 0; g < 4; g++) { acc[g][0] = 0ULL; acc[g][1] = 0ULL; }

        #pragma unroll 1
        for (int blk = 0; blk < 8; blk++) {
            cp_wait0();
            __syncthreads();
            if (blk < 7) {                       // prefetch next block
                int nbuf = (blk + 1) & 1, k0n = (blk + 1) * 128;
                #pragma unroll
                for (int i = 0; i < 8; i++) {
                    int id = t + 256 * i, row = id >> 5, ck = id & 31;
                    cp_async16(hs_base + (unsigned)(nbuf * HS_SIZE + row * HS_STRIDE + ck * 4) * 4,
                               ht_in + row * NHID_D + k0n + ck * 4);
                }
                cp_commit();
            }
            const float* hb0 = hsm + (blk & 1) * HS_SIZE + b0 * HS_STRIDE;
            const float* hb1 = hsm + (blk & 1) * HS_SIZE + b1 * HS_STRIDE;
            const float* wsb = ws + blk * 128;
            #pragma unroll 8
            for (int kk = 0; kk < 128; kk += 4) {
                ulonglong2 h0 = *(const ulonglong2*)&hb0[kk];
                ulonglong2 h1 = *(const ulonglong2*)&hb1[kk];
                #pragma unroll
                for (int g = 0; g < 4; g++) {
                    ulonglong2 wv = *(const ulonglong2*)&wsb[wrow[g] + kk];
                    ffma2(acc[g][0], h0.x, wv.x);
                    ffma2(acc[g][0], h0.y, wv.y);
                    ffma2(acc[g][1], h1.x, wv.x);
                    ffma2(acc[g][1], h1.y, wv.y);
                }
            }
        }

        // epilogue: fully in registers
        float gate0[4], gate1[4];
        #pragma unroll
        for (int g = 0; g < 4; g++) {
            float bb = is_dec ? bD[g] : bE[g];
            float2 p = unpack2(acc[g][0]);
            gate0[g] = p.x + p.y + xv0[g] + bb;
            p = unpack2(acc[g][1]);
            gate1[g] = p.x + p.y + xv1[g] + bb;
        }
        {
            float gi = 1.f / (1.f + expf(-gate0[0]));
            float gf = 1.f / (1.f + expf(-gate0[1]));
            float gc = tanhf(gate0[2]);
            float go = 1.f / (1.f + expf(-gate0[3]));
            float cn = fmaf(gf, creg[0], gi * gc);
            float hn = go * tanhf(cn);
            if (!is_dec && m0v == 0.f) { hn = hreg[0]; cn = creg[0]; }
            creg[0] = cn; hreg[0] = hn;
        }
        {
            float gi = 1.f / (1.f + expf(-gate1[0]));
            float gf = 1.f / (1.f + expf(-gate1[1]));
            float gc = tanhf(gate1[2]);
            float go = 1.f / (1.f + expf(-gate1[3]));
            float cn = fmaf(gf, creg[1], gi * gc);
            float hn = go * tanhf(cn);
            if (!is_dec && m1v == 0.f) { hn = hreg[1]; cn = creg[1]; }
            creg[1] = cn; hreg[1] = hn;
        }
        __stcg(&ht_out[b0 * NHID_D + u], hreg[0]);
        __stcg(&ht_out[b1 * NHID_D + u], hreg[1]);
        if (is_dec) {
            out[((size_t)step * BATCH + b0) * NHID_D + u] = hreg[0];
            out[((size_t)step * BATCH + b1) * NHID_D + u] = hreg[1];
        }

        grid_barrier((unsigned)(gstep + 1));
    }
}

// ---------------- launch ----------------------------------------------------
extern "C" void kernel_launch(void* const* d_in, const int* in_sizes, int n_in,
                              void* d_out, int out_size) {
    const float* input    = (const float*)d_in[0];  // [512,64,512]
    const float* mask     = (const float*)d_in[1];  // [512,64]
    const float* W_ih_enc = (const float*)d_in[2];  // [4096,512]
    const float* W_hh_enc = (const float*)d_in[3];  // [4096,1024]
    const float* b_ih_enc = (const float*)d_in[4];  // [4096]
    const float* b_hh_enc = (const float*)d_in[5];  // [4096]
    const float* W_ih_dec = (const float*)d_in[6];
    const float* W_hh_dec = (const float*)d_in[7];
    const float* b_ih_dec = (const float*)d_in[8];
    const float* b_hh_dec = (const float*)d_in[9];
    float* out = (float*)d_out;                     // [32768,1024]

    const int rnn_smem = (32 * WS_STRIDE + 2 * HS_SIZE) * 4;   // 199168 B
    cudaFuncSetAttribute(rnn_persist, cudaFuncAttributeMaxDynamicSharedMemorySize, rnn_smem);

    init_state<<<(BATCH * NHID_D + 255) / 256, 256>>>();

    dim3 gg(NGATE / 64, (T_STEPS * BATCH) / 64);
    gemm_xw<<<gg, 256>>>(input, W_ih_enc, b_ih_enc, 0);
    gemm_xw<<<gg, 256>>>(input, W_ih_dec, b_ih_dec, 1);

    rnn_persist<<<NCTA_R, 256, rnn_smem>>>(W_hh_enc, W_hh_dec, b_hh_enc, b_hh_dec, mask, out);
}

// round 4
// speedup vs baseline: 3.1624x; 1.1387x over previous
#include <cuda_runtime.h>
#include <math.h>

#define T_STEPS 512
#define BATCH   64
#define NINP_D  512
#define NHID_D  1024
#define NGATE   4096   // 4*NHID
#define NCTA_R  128

typedef unsigned long long ull;

// ---------------- scratch (device globals; no runtime allocation) ----------
__device__ float g_xw_enc[(size_t)T_STEPS * BATCH * NGATE]; // 512 MB
__device__ float g_xw_dec[(size_t)T_STEPS * BATCH * NGATE]; // 512 MB
__device__ float g_h[2][BATCH * NHID_D];                    // h [b][u], ping-pong
__device__ unsigned g_arrive;
__device__ unsigned g_release;

// ---------------- helpers ---------------------------------------------------
__device__ __forceinline__ void ffma2(ull& d, ull a, ull b) {
    asm("fma.rn.f32x2 %0, %1, %2, %0;" : "+l"(d) : "l"(a), "l"(b));
}
__device__ __forceinline__ float2 unpack2(ull v) {
    float2 r; asm("mov.b64 {%0,%1}, %2;" : "=f"(r.x), "=f"(r.y) : "l"(v)); return r;
}
__device__ __forceinline__ ull pack2(float x, float y) {
    ull r; asm("mov.b64 %0, {%1,%2};" : "=l"(r) : "f"(x), "f"(y)); return r;
}
__device__ __forceinline__ void cp_async16(unsigned s, const void* g) {
    asm volatile("cp.async.cg.shared.global [%0], [%1], 16;" :: "r"(s), "l"(g));
}
__device__ __forceinline__ void cp_commit() { asm volatile("cp.async.commit_group;"); }
__device__ __forceinline__ void cp_wait0()  { asm volatile("cp.async.wait_group 0;" ::: "memory"); }

// ---------------- init ------------------------------------------------------
__global__ void init_state() {
    int i = blockIdx.x * blockDim.x + threadIdx.x;
    if (i == 0) { g_arrive = 0; g_release = 0; }
    if (i < BATCH * NHID_D) { g_h[0][i] = 0.f; g_h[1][i] = 0.f; }
}

// ---------------- phase 1: xW = input @ W_ih^T + b_ih ----------------------
// 128x128 CTA tile, 8x8 per thread, kk-pair f32x2 packing, cp.async dbuf.
// smem ull layout [row][GP] (GP=10 pad, 16B-aligned), data kkp 0..7.
#define GP 10
__global__ __launch_bounds__(256) void gemm_xw(const float* __restrict__ A,
                                               const float* __restrict__ W,
                                               const float* __restrict__ bias,
                                               int which) {
    float* C = which ? g_xw_dec : g_xw_enc;
    __shared__ ull Ab[2][128 * GP];
    __shared__ ull Bb[2][128 * GP];
    int t = threadIdx.x;
    int tm = t & 15, tn = t >> 4;
    int lrow = t >> 1, lk = t & 1;                 // loader: row, 8-float half
    size_t m0 = (size_t)blockIdx.y * 128, n0 = (size_t)blockIdx.x * 128;

    unsigned sa = (unsigned)__cvta_generic_to_shared(Ab);
    unsigned sb = (unsigned)__cvta_generic_to_shared(Bb);
    unsigned dstA0 = sa + (unsigned)(lrow * GP + lk * 4) * 8;
    unsigned dstB0 = sb + (unsigned)(lrow * GP + lk * 4) * 8;
    const float* srcA = A + (m0 + lrow) * NINP_D + lk * 8;
    const float* srcB = W + (n0 + lrow) * NINP_D + lk * 8;
    const unsigned bufB = 128 * GP * 8;            // bytes per buffer

    ull acc[8][8];
    #pragma unroll
    for (int i = 0; i < 8; i++)
        #pragma unroll
        for (int j = 0; j < 8; j++) acc[i][j] = 0ULL;

    // prologue: load block 0
    cp_async16(dstA0, srcA);
    cp_async16(dstA0 + 16, srcA + 4);
    cp_async16(dstB0, srcB);
    cp_async16(dstB0 + 16, srcB + 4);
    cp_commit();

    for (int kb = 0; kb < NINP_D / 16; kb++) {
        cp_wait0();
        __syncthreads();
        if (kb < NINP_D / 16 - 1) {
            int nb = (kb + 1) & 1, k0n = (kb + 1) * 16;
            cp_async16(dstA0 + nb * bufB, srcA + k0n);
            cp_async16(dstA0 + nb * bufB + 16, srcA + k0n + 4);
            cp_async16(dstB0 + nb * bufB, srcB + k0n);
            cp_async16(dstB0 + nb * bufB + 16, srcB + k0n + 4);
            cp_commit();
        }
        const ull* Ap = Ab[kb & 1];
        const ull* Bp = Bb[kb & 1];
        #pragma unroll
        for (int kkp = 0; kkp < 8; kkp++) {
            ull a[8], b[8];
            #pragma unroll
            for (int i = 0; i < 8; i++) a[i] = Ap[(tm + 16 * i) * GP + kkp];
            #pragma unroll
            for (int j = 0; j < 8; j++) b[j] = Bp[(tn + 16 * j) * GP + kkp];
            #pragma unroll
            for (int i = 0; i < 8; i++)
                #pragma unroll
                for (int j = 0; j < 8; j++)
                    ffma2(acc[i][j], a[i], b[j]);
        }
    }

    float bv[8];
    #pragma unroll
    for (int j = 0; j < 8; j++) bv[j] = bias[n0 + tn + 16 * j];
    #pragma unroll
    for (int i = 0; i < 8; i++) {
        size_t rowoff = (m0 + tm + 16 * i) * NGATE + n0;
        #pragma unroll
        for (int j = 0; j < 8; j++) {
            float2 p = unpack2(acc[i][j]);
            C[rowoff + tn + 16 * j] = p.x + p.y + bv[j];
        }
    }
}

// ---------------- grid barrier (validated) ----------------------------------
__device__ __forceinline__ void grid_barrier(unsigned target) {
    __threadfence();
    __syncthreads();
    if (threadIdx.x == 0) {
        unsigned prev = atomicAdd(&g_arrive, 1);
        if (prev == target * (unsigned)NCTA_R - 1) {
            atomicExch(&g_release, target);
        } else {
            while (*(volatile unsigned*)&g_release < target) __nanosleep(32);
        }
        __threadfence();
    }
    __syncthreads();
}

// ---------------- persistent recurrence ------------------------------------
// 128 CTAs x 256 threads. CTA owns 8 units x 4 gates = 32 cols.
// lane -> col (g=lane>>3, uu=lane&7); warp w -> k-slice [128w, 128w+128).
// W_hh slice lives in 64 f32x2 REGISTERS per thread for the whole direction.
// h[8 batches][1024k] double-buffered in smem; inner loads are warp-uniform
// LDS.128 broadcasts. Per-warp partials reduced 8-way via smem.
#define RED_STRIDE 33
#define HGRP (8 * 1024)            // floats per h group buffer

extern __shared__ float smem_dyn[];

__global__ __launch_bounds__(256) void rnn_persist(
        const float* __restrict__ W_enc, const float* __restrict__ W_dec,
        const float* __restrict__ bhh_enc, const float* __restrict__ bhh_dec,
        const float* __restrict__ mask, float* __restrict__ out) {
    float* hbuf = smem_dyn;                    // [2][8][1024]
    float* red  = smem_dyn + 2 * HGRP;         // [8][64][RED_STRIDE]

    int t    = threadIdx.x;
    int lane = t & 31, w = t >> 5;
    int g    = lane >> 3, uu = lane & 7;
    int u0   = blockIdx.x * 8;
    int euu  = t & 7, ebb = t >> 3;            // epilogue cell ids

    float bE[4], bD[4];
    #pragma unroll
    for (int g4 = 0; g4 < 4; g4++) {
        bE[g4] = bhh_enc[g4 * NHID_D + u0 + euu];
        bD[g4] = bhh_dec[g4 * NHID_D + u0 + euu];
    }

    ull w2[64];
    float creg[2] = {0.f, 0.f};
    float hreg[2] = {0.f, 0.f};
    unsigned hb_base = (unsigned)__cvta_generic_to_shared(hbuf);

    for (int gstep = 0; gstep < 2 * T_STEPS; gstep++) {
        int is_dec = gstep >= T_STEPS;
        int step   = gstep & (T_STEPS - 1);
        const float* ht_in  = g_h[gstep & 1];
        float*       ht_out = g_h[(gstep + 1) & 1];
        const float* xw = (is_dec ? g_xw_dec : g_xw_enc) + (size_t)step * BATCH * NGATE;

        // load W slice into registers once per direction
        if (gstep == 0 || gstep == T_STEPS) {
            const float* wr = (is_dec ? W_dec : W_enc)
                            + (size_t)(g * NHID_D + u0 + uu) * NHID_D + 128 * w;
            #pragma unroll
            for (int j = 0; j < 32; j++) {
                float4 v = __ldg((const float4*)(wr + 4 * j));
                w2[2 * j]     = pack2(v.x, v.y);
                w2[2 * j + 1] = pack2(v.z, v.w);
            }
        }

        // prefetch xw + mask for this thread's epilogue cells
        float xv0[4], xv1[4];
        #pragma unroll
        for (int g4 = 0; g4 < 4; g4++) {
            xv0[g4] = __ldcg(&xw[(size_t)ebb * NGATE + g4 * NHID_D + u0 + euu]);
            xv1[g4] = __ldcg(&xw[(size_t)(ebb + 32) * NGATE + g4 * NHID_D + u0 + euu]);
        }
        float m0v = 1.f, m1v = 1.f;
        if (!is_dec) {
            m0v = __ldg(&mask[(size_t)step * BATCH + ebb]);
            m1v = __ldg(&mask[(size_t)step * BATCH + ebb + 32]);
        }

        // issue h group 0 (batches 0..7, all k)
        #pragma unroll
        for (int i = 0; i < 8; i++) {
            int id = t + 256 * i, row = id >> 8, c4 = id & 255;
            cp_async16(hb_base + (unsigned)(row * 1024 + c4 * 4) * 4,
                       ht_in + row * NHID_D + c4 * 4);
        }
        cp_commit();

        for (int bg = 0; bg < 8; bg++) {
            cp_wait0();
            __syncthreads();
            if (bg < 7) {
                int nb = (bg + 1) & 1;
                const float* src = ht_in + (bg + 1) * 8 * NHID_D;
                #pragma unroll
                for (int i = 0; i < 8; i++) {
                    int id = t + 256 * i, row = id >> 8, c4 = id & 255;
                    cp_async16(hb_base + (unsigned)(nb * HGRP + row * 1024 + c4 * 4) * 4,
                               src + row * NHID_D + c4 * 4);
                }
                cp_commit();
            }
            const float* hb = hbuf + (bg & 1) * HGRP + 128 * w;
            #pragma unroll
            for (int half = 0; half < 2; half++) {
                ull acc2[4] = {0ULL, 0ULL, 0ULL, 0ULL};
                #pragma unroll
                for (int j = 0; j < 32; j++) {
                    #pragma unroll
                    for (int bb = 0; bb < 4; bb++) {
                        // warp-uniform address -> broadcast, 1 wavefront
                        ulonglong2 h4 = *(const ulonglong2*)&hb[(half * 4 + bb) * 1024 + 4 * j];
                        ffma2(acc2[bb], h4.x, w2[2 * j]);
                        ffma2(acc2[bb], h4.y, w2[2 * j + 1]);
                    }
                }
                #pragma unroll
                for (int bb = 0; bb < 4; bb++) {
                    float2 p = unpack2(acc2[bb]);
                    red[(w * 64 + bg * 8 + half * 4 + bb) * RED_STRIDE + lane] = p.x + p.y;
                }
            }
        }
        __syncthreads();

        // 8-way k-slice reduction + LSTM epilogue (cells (euu, ebb), (euu, ebb+32))
        #pragma unroll
        for (int cell = 0; cell < 2; cell++) {
            int b = ebb + 32 * cell;
            float gate[4];
            #pragma unroll
            for (int g4 = 0; g4 < 4; g4++) {
                float s = 0.f;
                #pragma unroll
                for (int ww = 0; ww < 8; ww++)
                    s += red[(ww * 64 + b) * RED_STRIDE + g4 * 8 + euu];
                float xv = cell ? xv1[g4] : xv0[g4];
                gate[g4] = s + xv + (is_dec ? bD[g4] : bE[g4]);
            }
            float gi = 1.f / (1.f + expf(-gate[0]));
            float gf = 1.f / (1.f + expf(-gate[1]));
            float gc = tanhf(gate[2]);
            float go = 1.f / (1.f + expf(-gate[3]));
            float cn = fmaf(gf, creg[cell], gi * gc);
            float hn = go * tanhf(cn);
            float mv = cell ? m1v : m0v;
            if (!is_dec && mv == 0.f) { hn = hreg[cell]; cn = creg[cell]; }
            creg[cell] = cn; hreg[cell] = hn;
            __stcg(&ht_out[b * NHID_D + u0 + euu], hn);
            if (is_dec)
                out[((size_t)step * BATCH + b) * NHID_D + u0 + euu] = hn;
        }

        grid_barrier((unsigned)(gstep + 1));
    }
}

// ---------------- launch ----------------------------------------------------
extern "C" void kernel_launch(void* const* d_in, const int* in_sizes, int n_in,
                              void* d_out, int out_size) {
    const float* input    = (const float*)d_in[0];  // [512,64,512]
    const float* mask     = (const float*)d_in[1];  // [512,64]
    const float* W_ih_enc = (const float*)d_in[2];  // [4096,512]
    const float* W_hh_enc = (const float*)d_in[3];  // [4096,1024]
    const float* b_ih_enc = (const float*)d_in[4];  // [4096]
    const float* b_hh_enc = (const float*)d_in[5];  // [4096]
    const float* W_ih_dec = (const float*)d_in[6];
    const float* W_hh_dec = (const float*)d_in[7];
    const float* b_ih_dec = (const float*)d_in[8];
    const float* b_hh_dec = (const float*)d_in[9];
    float* out = (float*)d_out;                     // [32768,1024]

    const int rnn_smem = (2 * HGRP + 8 * 64 * RED_STRIDE) * 4;   // 133,120 B
    cudaFuncSetAttribute(rnn_persist, cudaFuncAttributeMaxDynamicSharedMemorySize, rnn_smem);

    init_state<<<(BATCH * NHID_D + 255) / 256, 256>>>();

    dim3 gg(NGATE / 128, (T_STEPS * BATCH) / 128);
    gemm_xw<<<gg, 256>>>(input, W_ih_enc, b_ih_enc, 0);
    gemm_xw<<<gg, 256>>>(input, W_ih_dec, b_ih_dec, 1);

    rnn_persist<<<NCTA_R, 256, rnn_smem>>>(W_hh_enc, W_hh_dec, b_hh_enc, b_hh_dec, mask, out);
}

// round 7
// speedup vs baseline: 5.1834x; 1.6391x over previous
#include <cuda_runtime.h>
#include <math.h>
#include <stdint.h>

#define T_STEPS 512
#define BATCH   64
#define NINP_D  512
#define NHID_D  1024
#define NGATE   4096   // 4*NHID
#define NCTA_R  128

typedef unsigned long long ull;

// ---------------- scratch (device globals; no runtime allocation) ----------
__device__ float g_xw_enc[(size_t)T_STEPS * BATCH * NGATE]; // 512 MB
__device__ float g_xw_dec[(size_t)T_STEPS * BATCH * NGATE]; // 512 MB
__device__ float g_h[2][BATCH * NHID_D];                    // h [b][u], tf32-rounded, ping-pong
__device__ unsigned g_arrive;
__device__ unsigned g_release;

// ---------------- generic helpers ------------------------------------------
__device__ __forceinline__ void ffma2(ull& d, ull a, ull b) {
    asm("fma.rn.f32x2 %0, %1, %2, %0;" : "+l"(d) : "l"(a), "l"(b));
}
__device__ __forceinline__ float2 unpack2(ull v) {
    float2 r; asm("mov.b64 {%0,%1}, %2;" : "=f"(r.x), "=f"(r.y) : "l"(v)); return r;
}
__device__ __forceinline__ void cp_async16(unsigned s, const void* g) {
    asm volatile("cp.async.cg.shared.global [%0], [%1], 16;" :: "r"(s), "l"(g));
}
__device__ __forceinline__ void cp_commit() { asm volatile("cp.async.commit_group;"); }
__device__ __forceinline__ void cp_wait0()  { asm volatile("cp.async.wait_group 0;" ::: "memory"); }
__device__ __forceinline__ void cp_wait1()  { asm volatile("cp.async.wait_group 1;" ::: "memory"); }

__device__ __forceinline__ uint32_t tf32r_bits(float x) {
    uint32_t u; asm("cvt.rna.tf32.f32 %0, %1;" : "=r"(u) : "f"(x)); return u;
}
__device__ __forceinline__ float tf32r(float x) { return __uint_as_float(tf32r_bits(x)); }

// tf32 mma.sync (sm_80+, arch-portable): D[16x8] += A[16x8] * B[8x8]
__device__ __forceinline__ void mma_tf32(float& c0, float& c1, float& c2, float& c3,
                                         uint32_t a0, uint32_t a1, uint32_t a2, uint32_t a3,
                                         uint32_t b0, uint32_t b1) {
    asm("mma.sync.aligned.m16n8k8.row.col.f32.tf32.tf32.f32 "
        "{%0,%1,%2,%3}, {%4,%5,%6,%7}, {%8,%9}, {%0,%1,%2,%3};"
        : "+f"(c0), "+f"(c1), "+f"(c2), "+f"(c3)
        : "r"(a0), "r"(a1), "r"(a2), "r"(a3), "r"(b0), "r"(b1));
}

// ---------------- init ------------------------------------------------------
__global__ void init_state() {
    int i = blockIdx.x * blockDim.x + threadIdx.x;
    if (i == 0) { g_arrive = 0; g_release = 0; }
    if (i < BATCH * NHID_D) { g_h[0][i] = 0.f; g_h[1][i] = 0.f; }
}

// ---------------- phase 1: xW = input @ W_ih^T + b_ih (validated R4) --------
#define GP 10
__global__ __launch_bounds__(256) void gemm_xw(const float* __restrict__ A,
                                               const float* __restrict__ W,
                                               const float* __restrict__ bias,
                                               int which) {
    float* C = which ? g_xw_dec : g_xw_enc;
    __shared__ ull Ab[2][128 * GP];
    __shared__ ull Bb[2][128 * GP];
    int t = threadIdx.x;
    int tm = t & 15, tn = t >> 4;
    int lrow = t >> 1, lk = t & 1;
    size_t m0 = (size_t)blockIdx.y * 128, n0 = (size_t)blockIdx.x * 128;

    unsigned sa = (unsigned)__cvta_generic_to_shared(Ab);
    unsigned sb = (unsigned)__cvta_generic_to_shared(Bb);
    unsigned dstA0 = sa + (unsigned)(lrow * GP + lk * 4) * 8;
    unsigned dstB0 = sb + (unsigned)(lrow * GP + lk * 4) * 8;
    const float* srcA = A + (m0 + lrow) * NINP_D + lk * 8;
    const float* srcB = W + (n0 + lrow) * NINP_D + lk * 8;
    const unsigned bufB = 128 * GP * 8;

    ull acc[8][8];
    #pragma unroll
    for (int i = 0; i < 8; i++)
        #pragma unroll
        for (int j = 0; j < 8; j++) acc[i][j] = 0ULL;

    cp_async16(dstA0, srcA);
    cp_async16(dstA0 + 16, srcA + 4);
    cp_async16(dstB0, srcB);
    cp_async16(dstB0 + 16, srcB + 4);
    cp_commit();

    for (int kb = 0; kb < NINP_D / 16; kb++) {
        cp_wait0();
        __syncthreads();
        if (kb < NINP_D / 16 - 1) {
            int nb = (kb + 1) & 1, k0n = (kb + 1) * 16;
            cp_async16(dstA0 + nb * bufB, srcA + k0n);
            cp_async16(dstA0 + nb * bufB + 16, srcA + k0n + 4);
            cp_async16(dstB0 + nb * bufB, srcB + k0n);
            cp_async16(dstB0 + nb * bufB + 16, srcB + k0n + 4);
            cp_commit();
        }
        const ull* Ap = Ab[kb & 1];
        const ull* Bp = Bb[kb & 1];
        #pragma unroll
        for (int kkp = 0; kkp < 8; kkp++) {
            ull a[8], b[8];
            #pragma unroll
            for (int i = 0; i < 8; i++) a[i] = Ap[(tm + 16 * i) * GP + kkp];
            #pragma unroll
            for (int j = 0; j < 8; j++) b[j] = Bp[(tn + 16 * j) * GP + kkp];
            #pragma unroll
            for (int i = 0; i < 8; i++)
                #pragma unroll
                for (int j = 0; j < 8; j++)
                    ffma2(acc[i][j], a[i], b[j]);
        }
    }

    float bv[8];
    #pragma unroll
    for (int j = 0; j < 8; j++) bv[j] = bias[n0 + tn + 16 * j];
    #pragma unroll
    for (int i = 0; i < 8; i++) {
        size_t rowoff = (m0 + tm + 16 * i) * NGATE + n0;
        #pragma unroll
        for (int j = 0; j < 8; j++) {
            float2 p = unpack2(acc[i][j]);
            C[rowoff + tn + 16 * j] = p.x + p.y + bv[j];
        }
    }
}

// ---------------- grid barrier (validated) ----------------------------------
__device__ __forceinline__ void grid_barrier(unsigned target) {
    __threadfence();
    __syncthreads();
    if (threadIdx.x == 0) {
        unsigned prev = atomicAdd(&g_arrive, 1);
        if (prev == target * (unsigned)NCTA_R - 1) {
            atomicExch(&g_release, target);
        } else {
            while (*(volatile unsigned*)&g_release < target) __nanosleep(32);
        }
        __threadfence();
    }
    __syncthreads();
}

// ---------------- persistent tf32 mma.sync recurrence ----------------------
// 128 CTAs x 256 thr. CTA cols c=0..31 <-> gate g=c>>3, unit uu=c&7
// (global col = g*1024 + u0 + uu). D[64 b][32 c] = h[64,1024] @ Wslice^T.
// Warp wid: wm=wid>>2 (rows 32wm..+32), wk=wid&3 (k-slice 32 within each
// 128-k chunk). W in padded smem (stride 1028 w), h chunks dbuf (stride 132 w)
// -> all fragment LDS.32 conflict-free (banks 4*gid+tid).
#define WST 1028
#define HST 132
#define HBW (64 * HST)            // words per h buffer
#define RST 34                    // reduce row stride (words)

extern __shared__ float smem_dyn[];

__device__ __forceinline__ void fill_chunk(unsigned hbase, const float* ht_in,
                                           int chunk, int buf, int t) {
    #pragma unroll
    for (int i = 0; i < 8; i++) {
        int id = t + 256 * i;
        int row = id >> 5, k4 = (id & 31) * 4;
        cp_async16(hbase + (unsigned)(buf * HBW + row * HST + k4) * 4,
                   ht_in + (size_t)row * NHID_D + chunk * 128 + k4);
    }
    cp_commit();
}

__global__ __launch_bounds__(256) void rnn_persist(
        const float* __restrict__ W_enc, const float* __restrict__ W_dec,
        const float* __restrict__ bhh_enc, const float* __restrict__ bhh_dec,
        const float* __restrict__ mask, float* __restrict__ out) {
    float* wtile = smem_dyn;                 // [32][WST]
    float* hbuf  = smem_dyn + 32 * WST;      // [2][64][HST]
    float* red   = hbuf;                     // overlay: [4][64][RST]
    unsigned hbase = (unsigned)__cvta_generic_to_shared(hbuf);
    const uint32_t* wb = (const uint32_t*)wtile;
    const uint32_t* hbw = (const uint32_t*)hbuf;

    int t = threadIdx.x, lane = t & 31, wid = t >> 5;
    int gid = lane >> 2, tid = lane & 3;
    int wm = wid >> 2, wk = wid & 3;
    int u0 = blockIdx.x * 8;
    // epilogue cell ownership: batch eb, units {2*eup, 2*eup+1}
    int eb = t & 63, eup = t >> 6;
    int gu = u0 + 2 * eup;

    float creg[2] = {0.f, 0.f};
    float hreg[2] = {0.f, 0.f};
    float breg[4][2];

    for (int gstep = 0; gstep < 2 * T_STEPS; gstep++) {
        int is_dec = gstep >= T_STEPS;
        int step   = gstep & (T_STEPS - 1);
        const float* ht_in  = g_h[gstep & 1];
        float*       ht_out = g_h[(gstep + 1) & 1];
        const float* xw = (is_dec ? g_xw_dec : g_xw_enc) + (size_t)step * BATCH * NGATE;

        if (step == 0) {
            // W slice -> smem (tf32-rounded). smem row c = g*8+uu.
            const float* Wh = is_dec ? W_dec : W_enc;
            int c  = t >> 3;
            int kb = (t & 7) * 128;
            const float* src = Wh + (size_t)((c >> 3) * NHID_D + u0 + (c & 7)) * NHID_D + kb;
            uint32_t* dst = (uint32_t*)(wtile + c * WST + kb);
            #pragma unroll 8
            for (int k = 0; k < 128; k += 4) {
                float4 v = __ldg((const float4*)(src + k));
                uint32_t x0 = tf32r_bits(v.x), x1 = tf32r_bits(v.y);
                uint32_t x2 = tf32r_bits(v.z), x3 = tf32r_bits(v.w);
                asm volatile("st.shared.v4.b32 [%0], {%1,%2,%3,%4};"
                             :: "l"(__cvta_generic_to_shared(dst + k)),
                                "r"(x0), "r"(x1), "r"(x2), "r"(x3));
            }
            #pragma unroll
            for (int g = 0; g < 4; g++) {
                const float* bh = is_dec ? bhh_dec : bhh_enc;
                float2 v = *(const float2*)(bh + g * NHID_D + gu);
                breg[g][0] = v.x; breg[g][1] = v.y;
            }
            __syncthreads();
        }

        // prefetch xw + mask for epilogue cells
        float xv[4][2];
        #pragma unroll
        for (int g = 0; g < 4; g++) {
            float2 v = __ldcg((const float2*)(xw + (size_t)eb * NGATE + g * NHID_D + gu));
            xv[g][0] = v.x; xv[g][1] = v.y;
        }
        float mv = 1.f;
        if (!is_dec) mv = __ldg(&mask[(size_t)step * BATCH + eb]);

        // mma mainloop over 8 k-chunks (double-buffered)
        float acc[2][4][4];
        #pragma unroll
        for (int mt = 0; mt < 2; mt++)
            #pragma unroll
            for (int nt = 0; nt < 4; nt++)
                #pragma unroll
                for (int r = 0; r < 4; r++) acc[mt][nt][r] = 0.f;

        fill_chunk(hbase, ht_in, 0, 0, t);
        #pragma unroll 1
        for (int c = 0; c < 8; c++) {
            if (c < 7) {
                fill_chunk(hbase, ht_in, c + 1, (c + 1) & 1, t);
                cp_wait1();
            } else {
                cp_wait0();
            }
            __syncthreads();
            const uint32_t* hb = hbw + (c & 1) * HBW;
            const uint32_t* wp = wb + c * 128;
            #pragma unroll
            for (int kk = 0; kk < 4; kk++) {
                int kl = wk * 32 + kk * 8;
                uint32_t a[2][4], bf[4][2];
                #pragma unroll
                for (int mt = 0; mt < 2; mt++) {
                    int rb = wm * 32 + mt * 16;
                    a[mt][0] = hb[(rb + gid) * HST + kl + tid];
                    a[mt][1] = hb[(rb + gid + 8) * HST + kl + tid];
                    a[mt][2] = hb[(rb + gid) * HST + kl + tid + 4];
                    a[mt][3] = hb[(rb + gid + 8) * HST + kl + tid + 4];
                }
                #pragma unroll
                for (int nt = 0; nt < 4; nt++) {
                    bf[nt][0] = wp[(nt * 8 + gid) * WST + kl + tid];
                    bf[nt][1] = wp[(nt * 8 + gid) * WST + kl + tid + 4];
                }
                #pragma unroll
                for (int mt = 0; mt < 2; mt++)
                    #pragma unroll
                    for (int nt = 0; nt < 4; nt++)
                        mma_tf32(acc[mt][nt][0], acc[mt][nt][1],
                                 acc[mt][nt][2], acc[mt][nt][3],
                                 a[mt][0], a[mt][1], a[mt][2], a[mt][3],
                                 bf[nt][0], bf[nt][1]);
            }
            __syncthreads();
        }

        // store k-partials (overlay on dead h buffers)
        #pragma unroll
        for (int mt = 0; mt < 2; mt++) {
            int r0 = wm * 32 + mt * 16 + gid;
            #pragma unroll
            for (int nt = 0; nt < 4; nt++) {
                int cc = nt * 8 + 2 * tid;
                *(float2*)&red[(wk * 64 + r0) * RST + cc] =
                    make_float2(acc[mt][nt][0], acc[mt][nt][1]);
                *(float2*)&red[(wk * 64 + r0 + 8) * RST + cc] =
                    make_float2(acc[mt][nt][2], acc[mt][nt][3]);
            }
        }
        __syncthreads();

        // 4-way reduce + LSTM epilogue: thread owns cells (eb, gu), (eb, gu+1)
        float gate[4][2];
        #pragma unroll
        for (int g = 0; g < 4; g++) {
            float2 s = make_float2(0.f, 0.f);
            #pragma unroll
            for (int k4 = 0; k4 < 4; k4++) {
                float2 v = *(const float2*)&red[(k4 * 64 + eb) * RST + g * 8 + 2 * eup];
                s.x += v.x; s.y += v.y;
            }
            gate[g][0] = s.x + xv[g][0] + breg[g][0];
            gate[g][1] = s.y + xv[g][1] + breg[g][1];
        }
        float hro[2], ho[2];
        #pragma unroll
        for (int j = 0; j < 2; j++) {
            float gi = 1.f / (1.f + expf(-gate[0][j]));
            float gf = 1.f / (1.f + expf(-gate[1][j]));
            float gc = tanhf(gate[2][j]);
            float go = 1.f / (1.f + expf(-gate[3][j]));
            float cn = fmaf(gf, creg[j], gi * gc);
            float hn = go * tanhf(cn);
            if (!is_dec && mv == 0.f) { hn = hreg[j]; cn = creg[j]; }
            creg[j] = cn;
            float hr = tf32r(hn);
            hreg[j] = hr;
            hro[j] = hr;
            ho[j]  = hn;
        }
        __stcg((float2*)(ht_out + (size_t)eb * NHID_D + gu), make_float2(hro[0], hro[1]));
        if (is_dec)
            *(float2*)(out + ((size_t)step * BATCH + eb) * NHID_D + gu) =
                make_float2(ho[0], ho[1]);

        grid_barrier((unsigned)(gstep + 1));
    }
}

// ---------------- launch ----------------------------------------------------
extern "C" void kernel_launch(void* const* d_in, const int* in_sizes, int n_in,
                              void* d_out, int out_size) {
    const float* input    = (const float*)d_in[0];  // [512,64,512]
    const float* mask     = (const float*)d_in[1];  // [512,64]
    const float* W_ih_enc = (const float*)d_in[2];  // [4096,512]
    const float* W_hh_enc = (const float*)d_in[3];  // [4096,1024]
    const float* b_ih_enc = (const float*)d_in[4];  // [4096]
    const float* b_hh_enc = (const float*)d_in[5];  // [4096]
    const float* W_ih_dec = (const float*)d_in[6];
    const float* W_hh_dec = (const float*)d_in[7];
    const float* b_ih_dec = (const float*)d_in[8];
    const float* b_hh_dec = (const float*)d_in[9];
    float* out = (float*)d_out;                     // [32768,1024]

    const int rnn_smem = (32 * WST + 2 * HBW) * 4;   // 199,168 B
    cudaFuncSetAttribute(rnn_persist, cudaFuncAttributeMaxDynamicSharedMemorySize, rnn_smem);

    init_state<<<(BATCH * NHID_D + 255) / 256, 256>>>();

    dim3 gg(NGATE / 128, (T_STEPS * BATCH) / 128);
    gemm_xw<<<gg, 256>>>(input, W_ih_enc, b_ih_enc, 0);
    gemm_xw<<<gg, 256>>>(input, W_ih_dec, b_ih_dec, 1);

    rnn_persist<<<NCTA_R, 256, rnn_smem>>>(W_hh_enc, W_hh_dec, b_hh_enc, b_hh_dec, mask, out);
}

// round 8
// speedup vs baseline: 7.4237x; 1.4322x over previous
#include <cuda_runtime.h>
#include <math.h>
#include <stdint.h>

#define T_STEPS 512
#define BATCH   64
#define NINP_D  512
#define NHID_D  1024
#define NGATE   4096   // 4*NHID
#define NCTA_R  128

// ---------------- scratch (device globals; no runtime allocation) ----------
__device__ float g_xw_enc[(size_t)T_STEPS * BATCH * NGATE]; // 512 MB
__device__ float g_xw_dec[(size_t)T_STEPS * BATCH * NGATE]; // 512 MB
__device__ float g_h[2][BATCH * NHID_D];                    // h [b][u], tf32-rounded, ping-pong
__device__ unsigned g_arr1[128];   // group counters (stride 8 -> 32B apart)
__device__ unsigned g_root;
__device__ unsigned g_release;

// ---------------- generic helpers ------------------------------------------
__device__ __forceinline__ void cp_async16(unsigned s, const void* g) {
    asm volatile("cp.async.cg.shared.global [%0], [%1], 16;" :: "r"(s), "l"(g));
}
__device__ __forceinline__ void cp_commit() { asm volatile("cp.async.commit_group;"); }
__device__ __forceinline__ void cp_wait0()  { asm volatile("cp.async.wait_group 0;" ::: "memory"); }
__device__ __forceinline__ void cp_wait1()  { asm volatile("cp.async.wait_group 1;" ::: "memory"); }

__device__ __forceinline__ uint32_t tf32r_bits(float x) {
    uint32_t u; asm("cvt.rna.tf32.f32 %0, %1;" : "=r"(u) : "f"(x)); return u;
}
__device__ __forceinline__ float tf32r(float x) { return __uint_as_float(tf32r_bits(x)); }

// tf32 mma.sync (sm_80+, arch-portable): D[16x8] += A[16x8] * B[8x8]
__device__ __forceinline__ void mma_tf32(float& c0, float& c1, float& c2, float& c3,
                                         uint32_t a0, uint32_t a1, uint32_t a2, uint32_t a3,
                                         uint32_t b0, uint32_t b1) {
    asm("mma.sync.aligned.m16n8k8.row.col.f32.tf32.tf32.f32 "
        "{%0,%1,%2,%3}, {%4,%5,%6,%7}, {%8,%9}, {%0,%1,%2,%3};"
        : "+f"(c0), "+f"(c1), "+f"(c2), "+f"(c3)
        : "r"(a0), "r"(a1), "r"(a2), "r"(a3), "r"(b0), "r"(b1));
}

// ---------------- init ------------------------------------------------------
__global__ void init_state() {
    int i = blockIdx.x * blockDim.x + threadIdx.x;
    if (i == 0) { g_root = 0; g_release = 0; }
    if (i < 128) g_arr1[i] = 0;
    if (i < BATCH * NHID_D) { g_h[0][i] = 0.f; g_h[1][i] = 0.f; }
}

// ---------------- phase 1: xW = input @ W_ih^T + b_ih (tf32 mma.sync) ------
// CTA 128x128, k-chunk 32 dbuf, 8 warps (4m x 2n), warp tile 32x64.
// Raw f32 bits fed as tf32 (HW truncation) -- error budget analyzed.
#define AST 36                   // smem row stride (words), ≡4 mod 32 -> conflict-free frags
#define GBUF (128 * AST)

extern __shared__ float dynsm[];

__global__ __launch_bounds__(256) void gemm_xw_tc(const float* __restrict__ A,
                                                  const float* __restrict__ W,
                                                  const float* __restrict__ bias,
                                                  int which) {
    float* C = which ? g_xw_dec : g_xw_enc;
    unsigned abase = (unsigned)__cvta_generic_to_shared(dynsm);
    unsigned bbase = abase + 2u * GBUF * 4u;
    const uint32_t* Asw = (const uint32_t*)dynsm;
    const uint32_t* Bsw = Asw + 2 * GBUF;

    int t = threadIdx.x, lane = t & 31, wid = t >> 5;
    int gid = lane >> 2, tid = lane & 3;
    int wm = wid & 3, wn = wid >> 2;
    size_t m0 = (size_t)blockIdx.y * 128, n0 = (size_t)blockIdx.x * 128;

    float acc[2][8][4];
    #pragma unroll
    for (int mt = 0; mt < 2; mt++)
        #pragma unroll
        for (int nt = 0; nt < 8; nt++)
            #pragma unroll
            for (int r = 0; r < 4; r++) acc[mt][nt][r] = 0.f;

#define GFILL(kb, buf) do {                                                     \
        _Pragma("unroll")                                                       \
        for (int i_ = 0; i_ < 4; i_++) {                                        \
            int id_ = t + 256 * i_;                                             \
            int row_ = id_ >> 3, q_ = id_ & 7;                                  \
            cp_async16(abase + (unsigned)((buf) * GBUF + row_ * AST + q_ * 4) * 4, \
                       A + (m0 + row_) * NINP_D + (kb) * 32 + q_ * 4);          \
            cp_async16(bbase + (unsigned)((buf) * GBUF + row_ * AST + q_ * 4) * 4, \
                       W + (n0 + row_) * NINP_D + (kb) * 32 + q_ * 4);          \
        }                                                                       \
        cp_commit();                                                            \
    } while (0)

    GFILL(0, 0);
    #pragma unroll 1
    for (int kb = 0; kb < NINP_D / 32; kb++) {
        if (kb < NINP_D / 32 - 1) { GFILL(kb + 1, (kb + 1) & 1); cp_wait1(); }
        else cp_wait0();
        __syncthreads();
        const uint32_t* Ap = Asw + (kb & 1) * GBUF;
        const uint32_t* Bp = Bsw + (kb & 1) * GBUF;
        #pragma unroll
        for (int kk = 0; kk < 4; kk++) {
            int kl = kk * 8;
            uint32_t a[2][4], b[8][2];
            #pragma unroll
            for (int mt = 0; mt < 2; mt++) {
                int rb = wm * 32 + mt * 16;
                a[mt][0] = Ap[(rb + gid) * AST + kl + tid];
                a[mt][1] = Ap[(rb + gid + 8) * AST + kl + tid];
                a[mt][2] = Ap[(rb + gid) * AST + kl + tid + 4];
                a[mt][3] = Ap[(rb + gid + 8) * AST + kl + tid + 4];
            }
            #pragma unroll
            for (int nt = 0; nt < 8; nt++) {
                int rn = wn * 64 + nt * 8;
                b[nt][0] = Bp[(rn + gid) * AST + kl + tid];
                b[nt][1] = Bp[(rn + gid) * AST + kl + tid + 4];
            }
            #pragma unroll
            for (int mt = 0; mt < 2; mt++)
                #pragma unroll
                for (int nt = 0; nt < 8; nt++)
                    mma_tf32(acc[mt][nt][0], acc[mt][nt][1],
                             acc[mt][nt][2], acc[mt][nt][3],
                             a[mt][0], a[mt][1], a[mt][2], a[mt][3],
                             b[nt][0], b[nt][1]);
        }
        __syncthreads();
    }
#undef GFILL

    #pragma unroll
    for (int nt = 0; nt < 8; nt++) {
        int col = (int)n0 + wn * 64 + nt * 8 + 2 * tid;
        float2 bv = *(const float2*)&bias[col];
        #pragma unroll
        for (int mt = 0; mt < 2; mt++) {
            int r0 = wm * 32 + mt * 16 + gid;
            *(float2*)&C[(m0 + r0) * NGATE + col] =
                make_float2(acc[mt][nt][0] + bv.x, acc[mt][nt][1] + bv.y);
            *(float2*)&C[(m0 + r0 + 8) * NGATE + col] =
                make_float2(acc[mt][nt][2] + bv.x, acc[mt][nt][3] + bv.y);
        }
    }
}

// ---------------- two-level grid barrier ------------------------------------
// arrive: after each thread's global h stores. 8 CTAs/group -> 16 groups -> root.
__device__ __forceinline__ void barrier_arrive(unsigned target) {
    __threadfence();
    __syncthreads();
    if (threadIdx.x == 0) {
        int grp = blockIdx.x >> 3;
        unsigned prev = atomicAdd(&g_arr1[grp * 8], 1u);
        if (prev == target * 8u - 1u) {
            unsigned pr = atomicAdd(&g_root, 1u);
            if (pr == target * 16u - 1u) atomicExch(&g_release, target);
        }
    }
}
__device__ __forceinline__ void barrier_wait(unsigned target) {
    if (threadIdx.x == 0) {
        while (*(volatile unsigned*)&g_release < target) __nanosleep(32);
        __threadfence();
    }
    __syncthreads();
}

// ---------------- persistent tf32 mma.sync recurrence (R7-validated core) ---
#define WST 1028
#define HST 132
#define HBW (64 * HST)            // words per h buffer
#define RST 34                    // reduce row stride (words)

__device__ __forceinline__ void fill_chunk(unsigned hbase, const float* ht_in,
                                           int chunk, int buf, int t) {
    #pragma unroll
    for (int i = 0; i < 8; i++) {
        int id = t + 256 * i;
        int row = id >> 5, k4 = (id & 31) * 4;
        cp_async16(hbase + (unsigned)(buf * HBW + row * HST + k4) * 4,
                   ht_in + (size_t)row * NHID_D + chunk * 128 + k4);
    }
    cp_commit();
}

__global__ __launch_bounds__(256) void rnn_persist(
        const float* __restrict__ W_enc, const float* __restrict__ W_dec,
        const float* __restrict__ bhh_enc, const float* __restrict__ bhh_dec,
        const float* __restrict__ mask, float* __restrict__ out) {
    float* wtile = dynsm;                 // [32][WST]
    float* hbuf  = dynsm + 32 * WST;      // [2][64][HST]
    float* red   = hbuf;                  // overlay: [4][64][RST]
    unsigned hbase = (unsigned)__cvta_generic_to_shared(hbuf);
    const uint32_t* wb = (const uint32_t*)wtile;
    const uint32_t* hbw = (const uint32_t*)hbuf;

    int t = threadIdx.x, lane = t & 31, wid = t >> 5;
    int gid = lane >> 2, tid = lane & 3;
    int wm = wid >> 2, wk = wid & 3;
    int u0 = blockIdx.x * 8;
    int eb = t & 63, eup = t >> 6;
    int gu = u0 + 2 * eup;

    float creg[2] = {0.f, 0.f};
    float hreg[2] = {0.f, 0.f};
    float breg[4][2];

    for (int gstep = 0; gstep < 2 * T_STEPS; gstep++) {
        int is_dec = gstep >= T_STEPS;
        int step   = gstep & (T_STEPS - 1);
        const float* ht_in  = g_h[gstep & 1];
        float*       ht_out = g_h[(gstep + 1) & 1];
        const float* xw = (is_dec ? g_xw_dec : g_xw_enc) + (size_t)step * BATCH * NGATE;

        if (step == 0) {
            // W slice -> smem (tf32-rounded). smem row c = g*8+uu.
            const float* Wh = is_dec ? W_dec : W_enc;
            int c  = t >> 3;
            int kb = (t & 7) * 128;
            const float* src = Wh + (size_t)((c >> 3) * NHID_D + u0 + (c & 7)) * NHID_D + kb;
            uint32_t* dst = (uint32_t*)(wtile + c * WST + kb);
            #pragma unroll 8
            for (int k = 0; k < 128; k += 4) {
                float4 v = __ldg((const float4*)(src + k));
                uint32_t x0 = tf32r_bits(v.x), x1 = tf32r_bits(v.y);
                uint32_t x2 = tf32r_bits(v.z), x3 = tf32r_bits(v.w);
                asm volatile("st.shared.v4.b32 [%0], {%1,%2,%3,%4};"
                             :: "l"(__cvta_generic_to_shared(dst + k)),
                                "r"(x0), "r"(x1), "r"(x2), "r"(x3));
            }
            #pragma unroll
            for (int g = 0; g < 4; g++) {
                const float* bh = is_dec ? bhh_dec : bhh_enc;
                float2 v = *(const float2*)(bh + g * NHID_D + gu);
                breg[g][0] = v.x; breg[g][1] = v.y;
            }
            __syncthreads();
        }

        // step-static prefetches (no h dependency) -> overlap with barrier wait
        float xv[4][2];
        #pragma unroll
        for (int g = 0; g < 4; g++) {
            float2 v = __ldcg((const float2*)(xw + (size_t)eb * NGATE + g * NHID_D + gu));
            xv[g][0] = v.x; xv[g][1] = v.y;
        }
        float mv = 1.f;
        if (!is_dec) mv = __ldg(&mask[(size_t)step * BATCH + eb]);

        barrier_wait((unsigned)gstep);

        // mma mainloop over 8 k-chunks (double-buffered)
        float acc[2][4][4];
        #pragma unroll
        for (int mt = 0; mt < 2; mt++)
            #pragma unroll
            for (int nt = 0; nt < 4; nt++)
                #pragma unroll
                for (int r = 0; r < 4; r++) acc[mt][nt][r] = 0.f;

        fill_chunk(hbase, ht_in, 0, 0, t);
        #pragma unroll 1
        for (int c = 0; c < 8; c++) {
            if (c < 7) {
                fill_chunk(hbase, ht_in, c + 1, (c + 1) & 1, t);
                cp_wait1();
            } else {
                cp_wait0();
            }
            __syncthreads();
            const uint32_t* hb = hbw + (c & 1) * HBW;
            const uint32_t* wp = wb + c * 128;
            #pragma unroll
            for (int kk = 0; kk < 4; kk++) {
                int kl = wk * 32 + kk * 8;
                uint32_t a[2][4], bf[4][2];
                #pragma unroll
                for (int mt = 0; mt < 2; mt++) {
                    int rb = wm * 32 + mt * 16;
                    a[mt][0] = hb[(rb + gid) * HST + kl + tid];
                    a[mt][1] = hb[(rb + gid + 8) * HST + kl + tid];
                    a[mt][2] = hb[(rb + gid) * HST + kl + tid + 4];
                    a[mt][3] = hb[(rb + gid + 8) * HST + kl + tid + 4];
                }
                #pragma unroll
                for (int nt = 0; nt < 4; nt++) {
                    bf[nt][0] = wp[(nt * 8 + gid) * WST + kl + tid];
                    bf[nt][1] = wp[(nt * 8 + gid) * WST + kl + tid + 4];
                }
                #pragma unroll
                for (int mt = 0; mt < 2; mt++)
                    #pragma unroll
                    for (int nt = 0; nt < 4; nt++)
                        mma_tf32(acc[mt][nt][0], acc[mt][nt][1],
                                 acc[mt][nt][2], acc[mt][nt][3],
                                 a[mt][0], a[mt][1], a[mt][2], a[mt][3],
                                 bf[nt][0], bf[nt][1]);
            }
            __syncthreads();
        }

        // store k-partials (overlay on dead h buffers)
        #pragma unroll
        for (int mt = 0; mt < 2; mt++) {
            int r0 = wm * 32 + mt * 16 + gid;
            #pragma unroll
            for (int nt = 0; nt < 4; nt++) {
                int cc = nt * 8 + 2 * tid;
                *(float2*)&red[(wk * 64 + r0) * RST + cc] =
                    make_float2(acc[mt][nt][0], acc[mt][nt][1]);
                *(float2*)&red[(wk * 64 + r0 + 8) * RST + cc] =
                    make_float2(acc[mt][nt][2], acc[mt][nt][3]);
            }
        }
        __syncthreads();

        // 4-way reduce + LSTM epilogue: thread owns cells (eb, gu), (eb, gu+1)
        float gate[4][2];
        #pragma unroll
        for (int g = 0; g < 4; g++) {
            float2 s = make_float2(0.f, 0.f);
            #pragma unroll
            for (int k4 = 0; k4 < 4; k4++) {
                float2 v = *(const float2*)&red[(k4 * 64 + eb) * RST + g * 8 + 2 * eup];
                s.x += v.x; s.y += v.y;
            }
            gate[g][0] = s.x + xv[g][0] + breg[g][0];
            gate[g][1] = s.y + xv[g][1] + breg[g][1];
        }
        float hro[2], ho[2];
        #pragma unroll
        for (int j = 0; j < 2; j++) {
            float gi = 1.f / (1.f + expf(-gate[0][j]));
            float gf = 1.f / (1.f + expf(-gate[1][j]));
            float gc = tanhf(gate[2][j]);
            float go = 1.f / (1.f + expf(-gate[3][j]));
            float cn = fmaf(gf, creg[j], gi * gc);
            float hn = go * tanhf(cn);
            if (!is_dec && mv == 0.f) { hn = hreg[j]; cn = creg[j]; }
            creg[j] = cn;
            float hr = tf32r(hn);
            hreg[j] = hr;
            hro[j] = hr;
            ho[j]  = hn;
        }
        __stcg((float2*)(ht_out + (size_t)eb * NHID_D + gu), make_float2(hro[0], hro[1]));

        barrier_arrive((unsigned)(gstep + 1));   // h published; out stores overlap peers

        if (is_dec)
            *(float2*)(out + ((size_t)step * BATCH + eb) * NHID_D + gu) =
                make_float2(ho[0], ho[1]);
    }
}

// ---------------- launch ----------------------------------------------------
extern "C" void kernel_launch(void* const* d_in, const int* in_sizes, int n_in,
                              void* d_out, int out_size) {
    const float* input    = (const float*)d_in[0];  // [512,64,512]
    const float* mask     = (const float*)d_in[1];  // [512,64]
    const float* W_ih_enc = (const float*)d_in[2];  // [4096,512]
    const float* W_hh_enc = (const float*)d_in[3];  // [4096,1024]
    const float* b_ih_enc = (const float*)d_in[4];  // [4096]
    const float* b_hh_enc = (const float*)d_in[5];  // [4096]
    const float* W_ih_dec = (const float*)d_in[6];
    const float* W_hh_dec = (const float*)d_in[7];
    const float* b_ih_dec = (const float*)d_in[8];
    const float* b_hh_dec = (const float*)d_in[9];
    float* out = (float*)d_out;                     // [32768,1024]

    const int gemm_smem = 4 * GBUF * 4;              // 73,728 B
    const int rnn_smem  = (32 * WST + 2 * HBW) * 4;  // 199,168 B
    cudaFuncSetAttribute(gemm_xw_tc, cudaFuncAttributeMaxDynamicSharedMemorySize, gemm_smem);
    cudaFuncSetAttribute(rnn_persist, cudaFuncAttributeMaxDynamicSharedMemorySize, rnn_smem);

    init_state<<<(BATCH * NHID_D + 255) / 256, 256>>>();

    dim3 gg(NGATE / 128, (T_STEPS * BATCH) / 128);
    gemm_xw_tc<<<gg, 256, gemm_smem>>>(input, W_ih_enc, b_ih_enc, 0);
    gemm_xw_tc<<<gg, 256, gemm_smem>>>(input, W_ih_dec, b_ih_dec, 1);

    rnn_persist<<<NCTA_R, 256, rnn_smem>>>(W_hh_enc, W_hh_dec, b_hh_enc, b_hh_dec, mask, out);
}